// round 5
// baseline (speedup 1.0000x reference)
#include <cuda_runtime.h>

// RankDPO loss, B=8192, K=64. Single fused kernel.
// softplus(x) = relu(x) + ln(1+e^{-|x|}); e^{-|x|} via ONE ex2.approx,
// ln(1+t) on (0,1] via degree-5 Chebyshev poly evaluated PACKED (fma.rn.f32x2)
// for both pairs of each iteration. MUFU count halved vs lg2-based version.
// Pair scheme: lane l owns (l, l+32); iteration k=1..31 handles
// A=(l, l+k) and B=(l+32, (l+32+k)&63) from one LDS.128 + one LDS.64 via the
// interleaved table P[m]={sL[m], sL[(m+32)&63], g[m], g[(m+32)&63]}, Q[m]={d,d'}.

#define ROWS_PER_BLOCK 8
#define THREADS 256
#define NUM_BLOCKS 1024                      // 8192 / 8
#define INV_PAIR_COUNT (1.0f / 16515072.0f)  // 8192 * 2016
#define LOG2E 1.4426950408889634f
#define LN2   0.6931471805599453f

// ln(1+t) on [0,1], deg-5 (Chebyshev of ln(3+u), u=2t-1, truncated; |err|~1e-5)
#define Q0 0.0000101f
#define Q1 0.9992360f
#define Q2 (-0.4902323f)
#define Q3 0.2852755f
#define Q4 (-0.1315843f)
#define Q5 0.0304498f

static __device__ float g_partials[NUM_BLOCKS];
static __device__ unsigned int g_ticket = 0;

typedef unsigned long long u64;

static __device__ __forceinline__ float ex2f(float x) {
    float y; asm("ex2.approx.f32 %0, %1;" : "=f"(y) : "f"(x)); return y;
}
static __device__ __forceinline__ u64 packf2(float lo, float hi) {
    u64 r; asm("mov.b64 %0, {%1, %2};" : "=l"(r) : "f"(lo), "f"(hi)); return r;
}
static __device__ __forceinline__ void unpackf2(float& lo, float& hi, u64 v) {
    asm("mov.b64 {%0, %1}, %2;" : "=f"(lo), "=f"(hi) : "l"(v));
}
static __device__ __forceinline__ u64 addx2(u64 a, u64 b) {
    u64 r; asm("add.rn.f32x2 %0, %1, %2;" : "=l"(r) : "l"(a), "l"(b)); return r;
}
static __device__ __forceinline__ u64 mulx2(u64 a, u64 b) {
    u64 r; asm("mul.rn.f32x2 %0, %1, %2;" : "=l"(r) : "l"(a), "l"(b)); return r;
}
static __device__ __forceinline__ u64 fmax2(u64 a, u64 b, u64 c) {
    u64 r; asm("fma.rn.f32x2 %0, %1, %2, %3;" : "=l"(r) : "l"(a), "l"(b), "l"(c)); return r;
}

__global__ __launch_bounds__(THREADS)
void rankdpo_fused(const float* __restrict__ S,
                   const float* __restrict__ R,
                   float* __restrict__ out) {
    __shared__ __align__(16) float4 Ptab[ROWS_PER_BLOCK][64];
    __shared__ __align__(8)  float2 Qtab[ROWS_PER_BLOCK][64];
    __shared__ __align__(16) float  rsh[ROWS_PER_BLOCK][64];
    __shared__ float wsum[ROWS_PER_BLOCK];
    __shared__ float red[THREADS];
    __shared__ int   isLast;

    const int warp = threadIdx.x >> 5;
    const int lane = threadIdx.x & 31;
    const int row  = blockIdx.x * ROWS_PER_BLOCK + warp;

    const float* srow = S + row * 64;
    const float* rrow = R + row * 64;
    const float s0 = srow[lane];
    const float s1 = srow[lane + 32];
    const float r0 = rrow[lane];
    const float r1 = rrow[lane + 32];

    float* rw = rsh[warp];
    rw[lane]      = r0;
    rw[lane + 32] = r1;
    __syncwarp();

    // ---- rank: count strictly-greater rewards (ties ~2^-23/pair, delta==0 there) ----
    int c0 = 0, c1 = 0;
    const float4* rv = (const float4*)rw;
    #pragma unroll
    for (int q = 0; q < 16; q++) {
        const float4 v = rv[q];
        c0 += (v.x > r0) + (v.y > r0) + (v.z > r0) + (v.w > r0);
        c1 += (v.x > r1) + (v.y > r1) + (v.z > r1) + (v.w > r1);
    }
    const float d0 = __fdividef(1.f, __logf((float)(c0 + 2)));
    const float d1 = __fdividef(1.f, __logf((float)(c1 + 2)));
    const float g0 = 2.f * r0 - 1.f;
    const float g1 = 2.f * r1 - 1.f;
    const float sL0 = s0 * LOG2E;   // lg2-domain score
    const float sL1 = s1 * LOG2E;

    // interleaved tables: entry m serves pair (m, .) and pair (m+32 side)
    Ptab[warp][lane]      = make_float4(sL0, sL1, g0, g1);
    Ptab[warp][lane + 32] = make_float4(sL1, sL0, g1, g0);
    Qtab[warp][lane]      = make_float2(d0, d1);
    Qtab[warp][lane + 32] = make_float2(d1, d0);
    __syncwarp();

    const u64 negS2 = packf2(-sL0, -sL1);
    const u64 negG2 = packf2(-g0, -g1);
    const u64 negD2 = packf2(-d0, -d1);
    const u64 q0_2 = packf2(Q0, Q0);
    const u64 q1_2 = packf2(Q1, Q1);
    const u64 q2_2 = packf2(Q2, Q2);
    const u64 q3_2 = packf2(Q3, Q3);
    const u64 q4_2 = packf2(Q4, Q4);
    const u64 q5_2 = packf2(Q5, Q5);

    const float4* Pb = &Ptab[warp][lane];
    const float2* Qb = &Qtab[warp][lane];

    float accR0 = 0.f, accR1 = 0.f;   // relu terms, lg2 domain
    float accP0 = 0.f, accP1 = 0.f;   // poly (ln1p) terms, natural domain
    #pragma unroll
    for (int k = 1; k < 32; k++) {
        const u64* pv = (const u64*)(Pb + k);
        const u64 sP = pv[0];                 // {sL[m], sL[(m+32)&63]}
        const u64 gP = pv[1];                 // {g[m],  g[(m+32)&63]}
        const u64 dP = *(const u64*)(Qb + k); // {d[m],  d[(m+32)&63]}

        const u64 x2     = addx2(sP, negS2);       // s_partner - s_own (lg2 dom)
        const u64 dg2    = addx2(gP, negG2);
        const u64 dd2    = addx2(dP, negD2);
        const u64 delta2 = mulx2(dg2, dd2);

        float xA, xB, dtA, dtB;
        unpackf2(xA, xB, x2);
        unpackf2(dtA, dtB, delta2);

        // t = e^{-|x_natural|} = 2^{-|x_lg2|}  (orientation-free)
        const float tA = ex2f(-fabsf(xA));
        const float tB = ex2f(-fabsf(xB));
        const u64 t2 = packf2(tA, tB);

        // packed Horner: p(t) ~= ln(1+t)
        u64 h = fmax2(t2, q5_2, q4_2);
        h = fmax2(t2, h, q3_2);
        h = fmax2(t2, h, q2_2);
        h = fmax2(t2, h, q1_2);
        h = fmax2(t2, h, q0_2);
        float pA, pB;
        unpackf2(pA, pB, h);

        // relu of the ORIENTED diff (lg2 domain).
        // A: partner index > own always. B: wraps (partner < own) iff lane+k >= 32.
        const float rA  = fmaxf(xA, 0.f);
        const float xBo = (lane + k < 32) ? xB : -xB;
        const float rB  = fmaxf(xBo, 0.f);

        accR0 = fmaf(fabsf(dtA), rA, accR0);
        accP0 = fmaf(fabsf(dtA), pA, accP0);
        accR1 = fmaf(fabsf(dtB), rB, accR1);
        accP1 = fmaf(fabsf(dtB), pB, accP1);
    }
    {   // gap-32 pair (lane, lane+32): i = lane+32 > j = lane
        const float delta = fabsf((g1 - g0) * (d1 - d0));
        const float x = sL1 - sL0;
        const float t = ex2f(-fabsf(x));
        const float p = Q0 + t*(Q1 + t*(Q2 + t*(Q3 + t*(Q4 + t*Q5))));
        accR0 = fmaf(delta, fmaxf(x, 0.f), accR0);
        accP0 += delta * p;
    }
    // natural-domain total: relu part carries log2e scaling -> multiply by ln2
    float acc = fmaf(accR0 + accR1, LN2, accP0 + accP1);

    // ---- warp reduce ----
    #pragma unroll
    for (int o = 16; o; o >>= 1)
        acc += __shfl_xor_sync(0xffffffffu, acc, o);
    if (lane == 0) wsum[warp] = acc;
    __syncthreads();

    if (threadIdx.x == 0) {
        float s = 0.f;
        #pragma unroll
        for (int w = 0; w < ROWS_PER_BLOCK; w++) s += wsum[w];
        g_partials[blockIdx.x] = s;
        __threadfence();
        const unsigned tk = atomicAdd(&g_ticket, 1u);
        isLast = (tk == (unsigned)(gridDim.x - 1));
    }
    __syncthreads();

    // ---- last block: deterministic fixed-order reduction of 1024 partials ----
    if (isLast) {
        const int tid = threadIdx.x;
        float v = g_partials[tid]
                + g_partials[tid + 256]
                + g_partials[tid + 512]
                + g_partials[tid + 768];
        red[tid] = v;
        __syncthreads();
        #pragma unroll
        for (int stride = THREADS / 2; stride > 0; stride >>= 1) {
            if (tid < stride) red[tid] += red[tid + stride];
            __syncthreads();
        }
        if (tid == 0) {
            out[0] = red[0] * INV_PAIR_COUNT;
            g_ticket = 0;   // reset for graph replay
        }
    }
}

extern "C" void kernel_launch(void* const* d_in, const int* in_sizes, int n_in,
                              void* d_out, int out_size) {
    (void)in_sizes; (void)n_in; (void)out_size;
    const float* s = (const float*)d_in[0];   // policy_logps
    const float* r = (const float*)d_in[1];   // reward_scores
    rankdpo_fused<<<NUM_BLOCKS, THREADS>>>(s, r, (float*)d_out);
}

// round 6
// speedup vs baseline: 1.1045x; 1.1045x over previous
#include <cuda_runtime.h>

// RankDPO loss, B=8192, K=64. Single fused kernel (R4 structure, leaner loop).
// Key facts used:
//  * delta = (g_i-g_j)*(d_i-d_j) >= 0 ALWAYS (g increasing in r, d increasing
//    in r via rank), so no fabs needed.
//  * orientation handled off the MUFU critical path: accumulate unoriented
//    lg2(1+2^x) for all pairs; for wrapped pairs add delta*x to a correction
//    accumulator (softplus(-x) = softplus(x) - x), subtract once at the end.
// Pair scheme: lane l owns (l, l+32); iter k=1..31 does A=(l,l+k) and
// B=(l+32,(l+32+k)&63) from one LDS.128 + one LDS.64 via interleaved tables.

#define ROWS_PER_BLOCK 8
#define THREADS 256
#define NUM_BLOCKS 1024                      // 8192 / 8
#define INV_PAIR_COUNT (1.0f / 16515072.0f)  // 8192 * 2016
#define LOG2E 1.4426950408889634f
#define LN2   0.6931471805599453f

static __device__ float g_partials[NUM_BLOCKS];
static __device__ unsigned int g_ticket = 0;

typedef unsigned long long u64;

static __device__ __forceinline__ float ex2f(float x) {
    float y; asm("ex2.approx.f32 %0, %1;" : "=f"(y) : "f"(x)); return y;
}
static __device__ __forceinline__ float lg2f(float x) {
    float y; asm("lg2.approx.f32 %0, %1;" : "=f"(y) : "f"(x)); return y;
}
static __device__ __forceinline__ u64 packf2(float lo, float hi) {
    u64 r; asm("mov.b64 %0, {%1, %2};" : "=l"(r) : "f"(lo), "f"(hi)); return r;
}
static __device__ __forceinline__ void unpackf2(float& lo, float& hi, u64 v) {
    asm("mov.b64 {%0, %1}, %2;" : "=f"(lo), "=f"(hi) : "l"(v));
}
static __device__ __forceinline__ u64 addx2(u64 a, u64 b) {
    u64 r; asm("add.rn.f32x2 %0, %1, %2;" : "=l"(r) : "l"(a), "l"(b)); return r;
}
static __device__ __forceinline__ u64 mulx2(u64 a, u64 b) {
    u64 r; asm("mul.rn.f32x2 %0, %1, %2;" : "=l"(r) : "l"(a), "l"(b)); return r;
}

__global__ __launch_bounds__(THREADS)
void rankdpo_fused(const float* __restrict__ S,
                   const float* __restrict__ R,
                   float* __restrict__ out) {
    __shared__ __align__(16) float4 Ptab[ROWS_PER_BLOCK][64];
    __shared__ __align__(8)  float2 Qtab[ROWS_PER_BLOCK][64];
    __shared__ __align__(16) float  rsh[ROWS_PER_BLOCK][64];
    __shared__ float wsum[ROWS_PER_BLOCK];
    __shared__ float red[THREADS];
    __shared__ int   isLast;

    const int warp = threadIdx.x >> 5;
    const int lane = threadIdx.x & 31;
    const int row  = blockIdx.x * ROWS_PER_BLOCK + warp;

    const float* srow = S + row * 64;
    const float* rrow = R + row * 64;
    const float s0 = srow[lane];
    const float s1 = srow[lane + 32];
    const float r0 = rrow[lane];
    const float r1 = rrow[lane + 32];

    float* rw = rsh[warp];
    rw[lane]      = r0;
    rw[lane + 32] = r1;
    __syncwarp();

    // ---- rank: count strictly-greater rewards (ties ~2^-23/pair; tied pairs
    //      have dg=0 -> delta=0, so dropped tie-break is harmless) ----
    int c0 = 0, c1 = 0;
    const float4* rv = (const float4*)rw;
    #pragma unroll
    for (int q = 0; q < 16; q++) {
        const float4 v = rv[q];
        c0 += (v.x > r0) + (v.y > r0) + (v.z > r0) + (v.w > r0);
        c1 += (v.x > r1) + (v.y > r1) + (v.z > r1) + (v.w > r1);
    }
    const float d0 = __fdividef(1.f, __logf((float)(c0 + 2)));
    const float d1 = __fdividef(1.f, __logf((float)(c1 + 2)));
    const float g0 = 2.f * r0 - 1.f;
    const float g1 = 2.f * r1 - 1.f;
    const float sL0 = s0 * LOG2E;   // lg2-domain score
    const float sL1 = s1 * LOG2E;

    // interleaved tables: entry m serves pair (m,.) and the (m+32)-side pair
    Ptab[warp][lane]      = make_float4(sL0, sL1, g0, g1);
    Ptab[warp][lane + 32] = make_float4(sL1, sL0, g1, g0);
    Qtab[warp][lane]      = make_float2(d0, d1);
    Qtab[warp][lane + 32] = make_float2(d1, d0);
    __syncwarp();

    const u64 negS2 = packf2(-sL0, -sL1);
    const u64 negG2 = packf2(-g0, -g1);
    const u64 negD2 = packf2(-d0, -d1);

    const float4* Pb = &Ptab[warp][lane];
    const float2* Qb = &Qtab[warp][lane];

    float acc0 = 0.f;   // pair-A softplus_lg2 terms
    float acc1 = 0.f;   // pair-B unoriented softplus_lg2 terms
    float accC = 0.f;   // pair-B wrapped correction: sum delta*x (lg2 domain)
    #pragma unroll
    for (int k = 1; k < 32; k++) {
        const u64* pv = (const u64*)(Pb + k);
        const u64 sP = pv[0];                 // {sL[m], sL[(m+32)&63]}
        const u64 gP = pv[1];                 // {g[m],  g[(m+32)&63]}
        const u64 dP = *(const u64*)(Qb + k); // {d[m],  d[(m+32)&63]}

        const u64 x2     = addx2(sP, negS2);  // s_partner - s_own (lg2 dom)
        const u64 dg2    = addx2(gP, negG2);
        const u64 dd2    = addx2(dP, negD2);
        const u64 delta2 = mulx2(dg2, dd2);   // >= 0 by monotonicity, no abs

        float xA, xB, dtA, dtB;
        unpackf2(xA, xB, x2);
        unpackf2(dtA, dtB, delta2);

        // pair A: partner index lane+k > lane always -> oriented as-is
        const float lA = lg2f(1.f + ex2f(xA));
        acc0 = fmaf(dtA, lA, acc0);

        // pair B: unoriented softplus; wrapped (lane+k>=32 -> partner < own)
        // oriented value = lB - xB, folded in via the correction accumulator
        const float lB = lg2f(1.f + ex2f(xB));
        acc1 = fmaf(dtB, lB, acc1);
        if (lane + k >= 32) accC = fmaf(dtB, xB, accC);
    }
    {   // gap-32 pair (lane, lane+32): i = lane+32 > j = lane
        const float delta = (g1 - g0) * (d1 - d0);   // >= 0
        acc0 = fmaf(delta, lg2f(1.f + ex2f(sL1 - sL0)), acc0);
    }
    float acc = (acc0 + acc1 - accC) * LN2;

    // ---- warp reduce ----
    #pragma unroll
    for (int o = 16; o; o >>= 1)
        acc += __shfl_xor_sync(0xffffffffu, acc, o);
    if (lane == 0) wsum[warp] = acc;
    __syncthreads();

    if (threadIdx.x == 0) {
        float s = 0.f;
        #pragma unroll
        for (int w = 0; w < ROWS_PER_BLOCK; w++) s += wsum[w];
        g_partials[blockIdx.x] = s;
        __threadfence();
        const unsigned tk = atomicAdd(&g_ticket, 1u);
        isLast = (tk == (unsigned)(gridDim.x - 1));
    }
    __syncthreads();

    // ---- last block: deterministic fixed-order reduction of 1024 partials ----
    if (isLast) {
        const int tid = threadIdx.x;
        float v = g_partials[tid]
                + g_partials[tid + 256]
                + g_partials[tid + 512]
                + g_partials[tid + 768];
        red[tid] = v;
        __syncthreads();
        #pragma unroll
        for (int stride = THREADS / 2; stride > 0; stride >>= 1) {
            if (tid < stride) red[tid] += red[tid + stride];
            __syncthreads();
        }
        if (tid == 0) {
            out[0] = red[0] * INV_PAIR_COUNT;
            g_ticket = 0;   // reset for graph replay
        }
    }
}

extern "C" void kernel_launch(void* const* d_in, const int* in_sizes, int n_in,
                              void* d_out, int out_size) {
    (void)in_sizes; (void)n_in; (void)out_size;
    const float* s = (const float*)d_in[0];   // policy_logps
    const float* r = (const float*)d_in[1];   // reward_scores
    rankdpo_fused<<<NUM_BLOCKS, THREADS>>>(s, r, (float*)d_out);
}